// round 1
// baseline (speedup 1.0000x reference)
#include <cuda_runtime.h>

// Binarized-weight 3x3 conv, stride 1, pad 1.
// x: (32,128,64,64) f32 NCHW ; w: (256,128,3,3) f32 OIHW -> sign(w)
// out: (32,256,64,64) f32
//
// CTA tile: one image, 64 couts, 4 output rows, all 64 columns.
// ci tiled by 8. fp32 exact, packed fma.rn.f32x2 (2 output columns / instr).

#define CI_TILE 8
#define CO_TILE 64
#define H_TILE 4

__device__ __forceinline__ unsigned long long pk2(float lo, float hi) {
    unsigned long long r;
    asm("mov.b64 %0, {%1, %2};" : "=l"(r) : "f"(lo), "f"(hi));
    return r;
}
__device__ __forceinline__ unsigned long long fma2(unsigned long long a,
                                                   unsigned long long b,
                                                   unsigned long long c) {
    unsigned long long d;
    asm("fma.rn.f32x2 %0, %1, %2, %3;" : "=l"(d) : "l"(a), "l"(b), "l"(c));
    return d;
}
__device__ __forceinline__ void upk2(unsigned long long v, float& lo, float& hi) {
    asm("mov.b64 {%0, %1}, %2;" : "=f"(lo), "=f"(hi) : "l"(v));
}

__global__ __launch_bounds__(256, 2)
void bconv3x3_kernel(const float* __restrict__ x,
                     const float* __restrict__ w,
                     float* __restrict__ out)
{
    // x halo tile: CI_TILE x 6 rows x 66 valid cols (stride 68 for 8B alignment)
    __shared__ float xs[CI_TILE * 6 * 68];
    // binarized weights: [ci][co_local][k]  (k = kh*3+kw)
    __shared__ float sw[CI_TILE * CO_TILE * 9];

    const int n   = blockIdx.z;
    const int co0 = blockIdx.y * CO_TILE;
    const int h0  = blockIdx.x * H_TILE;

    const int t    = threadIdx.x;
    const int lw   = t & 31;     // 32 threads across width
    const int cg   = t >> 5;     // 8 cout groups of 8
    const int wcol = lw * 2;     // output columns (wcol, wcol+1)

    unsigned long long acc[8][4];
#pragma unroll
    for (int j = 0; j < 8; j++)
#pragma unroll
        for (int h = 0; h < 4; h++) acc[j][h] = 0ull;

    for (int cib = 0; cib < 128 / CI_TILE; cib++) {
        const int cbase = cib * CI_TILE;

        // ---- stage x halo tile (zero-padded borders) ----
        for (int i = t; i < CI_TILE * 6 * 66; i += 256) {
            int ci  = i / 396;          // 6*66
            int rem = i - ci * 396;
            int r   = rem / 66;
            int c   = rem - r * 66;
            int gh  = h0 - 1 + r;
            int gw  = c - 1;
            float v = 0.f;
            if ((unsigned)gh < 64u && (unsigned)gw < 64u)
                v = x[(((size_t)n * 128 + cbase + ci) * 64 + gh) * 64 + gw];
            xs[(ci * 6 + r) * 68 + c] = v;
        }
        // ---- stage binarized weights ----
        for (int i = t; i < CI_TILE * CO_TILE * 9; i += 256) {
            int ci  = i / (CO_TILE * 9);
            int rem = i - ci * (CO_TILE * 9);
            int col = rem / 9;
            int k   = rem - col * 9;
            float wv = w[(((size_t)(co0 + col)) * 128 + cbase + ci) * 9 + k];
            sw[i] = (wv > 0.f) ? 1.f : ((wv < 0.f) ? -1.f : 0.f);
        }
        __syncthreads();

#pragma unroll 1
        for (int ci = 0; ci < CI_TILE; ci++) {
#pragma unroll
            for (int kh = 0; kh < 3; kh++) {
                // x pairs for the 3 kw taps, 4 output rows
                unsigned long long p0[4], p1[4], p2[4];
#pragma unroll
                for (int h = 0; h < 4; h++) {
                    const float* row = &xs[(ci * 6 + kh + h) * 68 + wcol];
                    const float2 a = *(const float2*)(row);      // x[w],   x[w+1]
                    const float2 b = *(const float2*)(row + 2);  // x[w+2], x[w+3]
                    p0[h] = pk2(a.x, a.y);
                    p1[h] = pk2(a.y, b.x);
                    p2[h] = pk2(b.x, b.y);
                }
#pragma unroll
                for (int j = 0; j < 8; j++) {
                    const int base = (ci * CO_TILE + cg * 8 + j) * 9 + kh * 3;
                    const float s0 = sw[base];
                    const float s1 = sw[base + 1];
                    const float s2 = sw[base + 2];
                    const unsigned long long ss0 = pk2(s0, s0);
                    const unsigned long long ss1 = pk2(s1, s1);
                    const unsigned long long ss2 = pk2(s2, s2);
#pragma unroll
                    for (int h = 0; h < 4; h++) {
                        unsigned long long v = fma2(ss2, p2[h], acc[j][h]);
                        v = fma2(ss1, p1[h], v);
                        acc[j][h] = fma2(ss0, p0[h], v);
                    }
                }
            }
        }
        __syncthreads();
    }

    // ---- epilogue ----
#pragma unroll
    for (int j = 0; j < 8; j++) {
        const int co = co0 + cg * 8 + j;
#pragma unroll
        for (int h = 0; h < 4; h++) {
            float lo, hi;
            upk2(acc[j][h], lo, hi);
            float2* dst = (float2*)&out[(((size_t)n * 256 + co) * 64 + h0 + h) * 64 + wcol];
            *dst = make_float2(lo, hi);
        }
    }
}

extern "C" void kernel_launch(void* const* d_in, const int* in_sizes, int n_in,
                              void* d_out, int out_size)
{
    const float* x = (const float*)d_in[0];
    const float* w = (const float*)d_in[1];
    float* out = (float*)d_out;

    dim3 grid(64 / H_TILE /*16 h-blocks*/, 256 / CO_TILE /*4 co-blocks*/, 32 /*n*/);
    bconv3x3_kernel<<<grid, 256>>>(x, w, out);
}